// round 2
// baseline (speedup 1.0000x reference)
#include <cuda_runtime.h>
#include <cstdint>

#define TT 512
#define BB 64
#define II 256
#define HH 512
#define NCTA 128

// 64MB scratch for the precomputed input contribution xw[t][b][h]
__device__ float g_xw[TT * BB * HH];
// Per-CTA progress flags for the chip-wide step barrier
__device__ volatile unsigned int g_flags[NCTA];

// ---------------------------------------------------------------------------
// Reset barrier flags (runs before the scan kernel on the same stream)
// ---------------------------------------------------------------------------
__global__ void reset_kernel() {
    if (threadIdx.x < NCTA) g_flags[threadIdx.x] = 0u;
}

// ---------------------------------------------------------------------------
// Phase 1: g_xw[m][h] = sum_i x[m][i] * W_ih[h][i] + b_ih[h] + b_hh[h]
//   A = x viewed as [M=32768, 256], W = W_ih [512, 256]
//   64x64 tiles, BK=32, 256 threads, 4x4 register tile per thread
// ---------------------------------------------------------------------------
__global__ __launch_bounds__(256) void phase1_kernel(
    const float* __restrict__ A,
    const float* __restrict__ W,
    const float* __restrict__ bih,
    const float* __restrict__ bhh)
{
    __shared__ float a_s[64][36];   // +4 pad, rows 16B aligned (36*4=144)
    __shared__ float w_s[64][36];

    const int tid = threadIdx.x;
    const int m0 = blockIdx.x * 64;
    const int n0 = blockIdx.y * 64;
    const int r0 = (tid & 15) * 4;   // row offset within tile
    const int c0 = (tid >> 4) * 4;   // col offset within tile

    float acc[4][4] = {};

    for (int k0 = 0; k0 < II; k0 += 32) {
        // Load 64x32 tiles of A and W (512 float4 each; 2 per thread)
        #pragma unroll
        for (int i = 0; i < 2; i++) {
            int idx = tid + i * 256;          // 0..511
            int row = idx >> 3;               // 0..63
            int kc  = (idx & 7) * 4;          // 0..28
            *(float4*)&a_s[row][kc] = *(const float4*)&A[(m0 + row) * II + k0 + kc];
            *(float4*)&w_s[row][kc] = *(const float4*)&W[(n0 + row) * II + k0 + kc];
        }
        __syncthreads();

        #pragma unroll
        for (int kq = 0; kq < 8; kq++) {
            float4 av[4], wv[4];
            #pragma unroll
            for (int i = 0; i < 4; i++) av[i] = *(float4*)&a_s[r0 + i][kq * 4];
            #pragma unroll
            for (int j = 0; j < 4; j++) wv[j] = *(float4*)&w_s[c0 + j][kq * 4];
            #pragma unroll
            for (int i = 0; i < 4; i++) {
                #pragma unroll
                for (int j = 0; j < 4; j++) {
                    acc[i][j] += av[i].x * wv[j].x;
                    acc[i][j] += av[i].y * wv[j].y;
                    acc[i][j] += av[i].z * wv[j].z;
                    acc[i][j] += av[i].w * wv[j].w;
                }
            }
        }
        __syncthreads();
    }

    // Epilogue: add biases, write to g_xw
    float b0 = bih[n0 + c0 + 0] + bhh[n0 + c0 + 0];
    float b1 = bih[n0 + c0 + 1] + bhh[n0 + c0 + 1];
    float b2 = bih[n0 + c0 + 2] + bhh[n0 + c0 + 2];
    float b3 = bih[n0 + c0 + 3] + bhh[n0 + c0 + 3];
    #pragma unroll
    for (int i = 0; i < 4; i++) {
        float4 o;
        o.x = acc[i][0] + b0;
        o.y = acc[i][1] + b1;
        o.z = acc[i][2] + b2;
        o.w = acc[i][3] + b3;
        *(float4*)&g_xw[(size_t)(m0 + r0 + i) * HH + n0 + c0] = o;
    }
}

// ---------------------------------------------------------------------------
// Phase 2: persistent scan kernel.
//   Grid = 128 CTAs (all co-resident). CTA (hb,bb) owns output tile
//   [16 hidden rows hb*16..] x [16 batches bb*16..]. Its W_hh row slice
//   (16x512 = 32KB) stays in SMEM for all 512 steps. Each step it stages the
//   16x512 h_prev slice from global (written by the 32 hb-CTAs last step),
//   computes 256 dot products (1 per thread, K=512, float4), applies relu,
//   writes to d_out[t], then passes a flag-array barrier.
// ---------------------------------------------------------------------------
__global__ __launch_bounds__(256) void scan_kernel(
    const float* __restrict__ Whh,
    float* out,
    int has_hfinal)
{
    extern __shared__ float smem[];
    float (*w_s)[516] = (float(*)[516])smem;               // 16 x 516
    float (*h_s)[516] = (float(*)[516])(smem + 16 * 516);  // 16 x 516

    const int tid = threadIdx.x;
    const int hb = blockIdx.x >> 2;    // 0..31  -> hidden block
    const int bb = blockIdx.x & 3;     // 0..3   -> batch block
    const int h0 = hb * 16;
    const int b0 = bb * 16;

    // Load W_hh rows [h0, h0+16) x [0,512): 2048 float4, 8 per thread
    #pragma unroll
    for (int i = 0; i < 8; i++) {
        int idx = tid + i * 256;       // 0..2047
        int row = idx >> 7;            // 0..15
        int kc  = (idx & 127) * 4;     // 0..508
        *(float4*)&w_s[row][kc] = *(const float4*)&Whh[(h0 + row) * HH + kc];
    }
    __syncthreads();

    // Thread -> (h_local, b_local): each warp covers 8 hidden x 4 batches
    // so the W-operand LDS is conflict-free and the h-operand is a broadcast.
    const int h_l = (tid & 7) | ((tid >> 7) << 3);   // 0..15
    const int b_l = (tid >> 3) & 15;                 // 0..15
    const int h = h0 + h_l;
    const int b = b0 + b_l;
    const float* wrow = &w_s[h_l][0];
    const float* hrow = &h_s[b_l][0];

    for (int t = 0; t < TT; t++) {
        // xw contribution (prefetched first: independent of h staging)
        float acc = g_xw[(size_t)(t * BB + b) * HH + h];

        if (t > 0) {
            // Stage h_prev slice: batches [b0, b0+16) of out[t-1]
            const float* src = out + (size_t)(t - 1) * BB * HH;
            #pragma unroll
            for (int i = 0; i < 8; i++) {
                int idx = tid + i * 256;
                int row = idx >> 7;
                int kc  = (idx & 127) * 4;
                *(float4*)&h_s[row][kc] = *(const float4*)&src[(b0 + row) * HH + kc];
            }
            __syncthreads();

            float a0 = 0.f, a1 = 0.f, a2 = 0.f, a3 = 0.f;
            #pragma unroll 8
            for (int k = 0; k < HH; k += 4) {
                float4 hv = *(const float4*)&hrow[k];
                float4 wv = *(const float4*)&wrow[k];
                a0 += hv.x * wv.x;
                a1 += hv.y * wv.y;
                a2 += hv.z * wv.z;
                a3 += hv.w * wv.w;
            }
            acc += (a0 + a1) + (a2 + a3);
        }

        float hval = fmaxf(acc, 0.0f);
        out[(size_t)(t * BB + b) * HH + h] = hval;
        if (has_hfinal && t == TT - 1) {
            out[(size_t)TT * BB * HH + b * HH + h] = hval;
        }

        // ----- chip-wide step barrier (flag array, parallel poll) -----
        __threadfence();                 // publish this thread's h store
        __syncthreads();                 // all threads of CTA fenced
        if (tid == 0) {
            g_flags[blockIdx.x] = (unsigned)(t + 1);   // volatile store
        }
        if (tid < NCTA) {
            unsigned want = (unsigned)(t + 1);
            while (g_flags[tid] < want) { /* spin on L2 */ }
        }
        __syncthreads();                 // CTA proceeds only when all 128 done
        // h_s is re-filled next iteration only after this barrier, so no
        // extra sync is needed before overwriting it.
    }
}

// ---------------------------------------------------------------------------
extern "C" void kernel_launch(void* const* d_in, const int* in_sizes, int n_in,
                              void* d_out, int out_size) {
    const float* x   = (const float*)d_in[0];   // [T,B,I]
    const float* wih = (const float*)d_in[1];   // [H,I]
    const float* whh = (const float*)d_in[2];   // [H,H]
    const float* bih = (const float*)d_in[3];   // [H]
    const float* bhh = (const float*)d_in[4];   // [H]
    float* out = (float*)d_out;

    const int has_hfinal = (out_size >= TT * BB * HH + BB * HH) ? 1 : 0;

    // Scan kernel needs 2 * 16 * 516 * 4 = 66048 B dynamic SMEM (> 48KB)
    static int attr_done = 0;
    const int smem_bytes = 2 * 16 * 516 * (int)sizeof(float);
    if (!attr_done) {
        cudaFuncSetAttribute(scan_kernel,
                             cudaFuncAttributeMaxDynamicSharedMemorySize,
                             smem_bytes);
        attr_done = 1;
    }

    reset_kernel<<<1, NCTA>>>();

    dim3 g1(TT * BB / 64, HH / 64);   // (512, 8)
    phase1_kernel<<<g1, 256>>>(x, wih, bih, bhh);

    scan_kernel<<<NCTA, 256, smem_bytes>>>(whh, out, has_hfinal);
}

// round 4
// speedup vs baseline: 2.0191x; 2.0191x over previous
#include <cuda_runtime.h>
#include <cstdint>

#define TT 512
#define BB 64
#define II 256
#define HH 512

// 64MB scratch for the precomputed input contribution xw[t][b][h]
__device__ float g_xw[TT * BB * HH];

// ---------------------------------------------------------------------------
// Phase 1: g_xw[m][h] = sum_i x[m][i] * W_ih[h][i] + b_ih[h] + b_hh[h]
// ---------------------------------------------------------------------------
__global__ __launch_bounds__(256) void phase1_kernel(
    const float* __restrict__ A,
    const float* __restrict__ W,
    const float* __restrict__ bih,
    const float* __restrict__ bhh)
{
    __shared__ float a_s[64][36];
    __shared__ float w_s[64][36];

    const int tid = threadIdx.x;
    const int m0 = blockIdx.x * 64;
    const int n0 = blockIdx.y * 64;
    const int r0 = (tid & 15) * 4;
    const int c0 = (tid >> 4) * 4;

    float acc[4][4] = {};

    for (int k0 = 0; k0 < II; k0 += 32) {
        #pragma unroll
        for (int i = 0; i < 2; i++) {
            int idx = tid + i * 256;
            int row = idx >> 3;
            int kc  = (idx & 7) * 4;
            *(float4*)&a_s[row][kc] = *(const float4*)&A[(m0 + row) * II + k0 + kc];
            *(float4*)&w_s[row][kc] = *(const float4*)&W[(n0 + row) * II + k0 + kc];
        }
        __syncthreads();

        #pragma unroll
        for (int kq = 0; kq < 8; kq++) {
            float4 av[4], wv[4];
            #pragma unroll
            for (int i = 0; i < 4; i++) av[i] = *(float4*)&a_s[r0 + i][kq * 4];
            #pragma unroll
            for (int j = 0; j < 4; j++) wv[j] = *(float4*)&w_s[c0 + j][kq * 4];
            #pragma unroll
            for (int i = 0; i < 4; i++) {
                #pragma unroll
                for (int j = 0; j < 4; j++) {
                    acc[i][j] += av[i].x * wv[j].x;
                    acc[i][j] += av[i].y * wv[j].y;
                    acc[i][j] += av[i].z * wv[j].z;
                    acc[i][j] += av[i].w * wv[j].w;
                }
            }
        }
        __syncthreads();
    }

    float b0 = bih[n0 + c0 + 0] + bhh[n0 + c0 + 0];
    float b1 = bih[n0 + c0 + 1] + bhh[n0 + c0 + 1];
    float b2 = bih[n0 + c0 + 2] + bhh[n0 + c0 + 2];
    float b3 = bih[n0 + c0 + 3] + bhh[n0 + c0 + 3];
    #pragma unroll
    for (int i = 0; i < 4; i++) {
        float4 o;
        o.x = acc[i][0] + b0;
        o.y = acc[i][1] + b1;
        o.z = acc[i][2] + b2;
        o.w = acc[i][3] + b3;
        *(float4*)&g_xw[(size_t)(m0 + r0 + i) * HH + n0 + c0] = o;
    }
}

// ---------------------------------------------------------------------------
// DSMEM / mbarrier helpers (cluster scope)
// ---------------------------------------------------------------------------
__device__ __forceinline__ uint32_t smem_u32(const void* p) {
    uint32_t a;
    asm("{ .reg .u64 t; cvta.to.shared.u64 t, %1; cvt.u32.u64 %0, t; }"
        : "=r"(a) : "l"(p));
    return a;
}

__device__ __forceinline__ void mbar_init(uint32_t mbar, uint32_t count) {
    asm volatile("mbarrier.init.shared.b64 [%0], %1;" :: "r"(mbar), "r"(count) : "memory");
}

// Wait with cluster-scope acquire (data arrives from peer CTAs' DSMEM stores).
__device__ __forceinline__ void mbar_wait_cluster(uint32_t mbar, uint32_t parity) {
    asm volatile(
        "{\n\t"
        ".reg .pred P;\n\t"
        "LW_%=:\n\t"
        "mbarrier.try_wait.parity.acquire.cluster.shared::cta.b64 P, [%0], %1, 0x989680;\n\t"
        "@P bra LD_%=;\n\t"
        "bra LW_%=;\n\t"
        "LD_%=:\n\t"
        "}"
        :: "r"(mbar), "r"(parity) : "memory");
}

// Release-arrive on the mbarrier at the same SMEM offset in CTA `rank`.
__device__ __forceinline__ void mbar_arrive_remote(uint32_t mbar_local, uint32_t rank) {
    asm volatile(
        "{\n\t"
        ".reg .b32 ra;\n\t"
        "mapa.shared::cluster.u32 ra, %0, %1;\n\t"
        "mbarrier.arrive.release.cluster.shared::cluster.b64 _, [ra];\n\t"
        "}"
        :: "r"(mbar_local), "r"(rank) : "memory");
}

// 8-byte DSMEM store into CTA `rank` at the same SMEM offset as `laddr`.
__device__ __forceinline__ void dsmem_st_b64(uint32_t laddr, uint32_t rank, float a, float b) {
    uint64_t v = ((uint64_t)__float_as_uint(b) << 32) | (uint64_t)__float_as_uint(a);
    asm volatile(
        "{\n\t"
        ".reg .b32 ra;\n\t"
        "mapa.shared::cluster.u32 ra, %0, %1;\n\t"
        "st.shared::cluster.b64 [ra], %2;\n\t"
        "}"
        :: "r"(laddr), "r"(rank), "l"(v) : "memory");
}

// ---------------------------------------------------------------------------
// Phase 2: cluster-based scan.
//   16 clusters x 8 CTAs. Cluster cid owns batches [4*cid, 4*cid+4).
//   CTA rank r owns hidden rows [64r, 64r+64); its W_hh slice lives in SMEM
//   transposed as w_T[k][h_local]. h state is exchanged ONLY within the
//   cluster via DSMEM pushes + mbarrier (no chip-wide sync, no global h).
//
// SMEM layout (floats):
//   [0, 32768)       w_T   [512][64]
//   [32768, 36864)   hbuf  [2][512][4]   (double-buffered h^T, [k][b])
//   [36864, 38912)   psum  [8][256]      (k-split partials)
//   [38912, 39168)   stage [64][4]       (this CTA's h slice, [h][b])
//   byte 156672:     full mbarriers [2]
// ---------------------------------------------------------------------------
#define SM_W     0
#define SM_HBUF  32768
#define SM_PSUM  36864
#define SM_STAGE 38912
#define SM_MBAR_BYTES (39168 * 4)
#define SM_TOTAL_BYTES (SM_MBAR_BYTES + 16)

__global__ void __cluster_dims__(8, 1, 1) __launch_bounds__(256, 1)
scan_kernel(const float* __restrict__ Whh, float* __restrict__ out, int has_hfinal)
{
    extern __shared__ float sm[];
    float* w_T   = sm + SM_W;
    float* hbuf  = sm + SM_HBUF;
    float* psum  = sm + SM_PSUM;
    float* stage = sm + SM_STAGE;

    const uint32_t smem_base = smem_u32(sm);
    const uint32_t mbar0 = smem_base + SM_MBAR_BYTES;
    const uint32_t mbar1 = mbar0 + 8;

    const int tid = threadIdx.x;
    uint32_t r;
    asm("mov.u32 %0, %%cluster_ctarank;" : "=r"(r));
    const int cid = blockIdx.x >> 3;
    const int b0 = cid * 4;           // 4 batches per cluster
    const int h0 = (int)r * 64;       // 64 hidden rows per CTA

    if (tid == 0) {
        mbar_init(mbar0, 8);
        mbar_init(mbar1, 8);
    }

    // Load W_hh rows [h0, h0+64) transposed into w_T[k][h_local].
    // (lanes walk h_local so STS is conflict-free; LDG is strided but one-time)
    for (int i = 0; i < 32; i++) {
        int idx = tid + i * 256;       // 0..8191 float4 ids
        int row = idx & 63;            // h_local
        int kq  = idx >> 6;            // 0..127
        float4 v = *(const float4*)&Whh[(size_t)(h0 + row) * HH + kq * 4];
        w_T[(kq * 4 + 0) * 64 + row] = v.x;
        w_T[(kq * 4 + 1) * 64 + row] = v.y;
        w_T[(kq * 4 + 2) * 64 + row] = v.z;
        w_T[(kq * 4 + 3) * 64 + row] = v.w;
    }
    __syncthreads();

    // All mbarriers initialized cluster-wide before any push/arrive.
    asm volatile("barrier.cluster.arrive.aligned;" ::: "memory");
    asm volatile("barrier.cluster.wait.aligned;" ::: "memory");

    // Compute role: k-split 8, thread tile 4h x 2b
    const int ks = tid >> 5;           // 0..7 -> k range [64*ks, 64*ks+64)
    const int u  = tid & 31;
    const int hq = u & 15;             // h quad: rows 4*hq..4*hq+3
    const int bp = u >> 4;             // batch pair: 2*bp, 2*bp+1
    const int kbase = ks * 64;

    // Reduction/output role: one (b_local, h_local) per thread
    const int rb = tid >> 6;           // 0..3
    const int rh = tid & 63;           // 0..63
    const size_t out_off_bh = (size_t)(b0 + rb) * HH + (h0 + rh);

    int ph0 = 0, ph1 = 0;

    for (int t = 0; t < TT; t++) {
        const int p = t & 1;

        // Prefetch xw BEFORE the barrier wait (latency fully hidden)
        float xwv = g_xw[(size_t)t * (BB * HH) + out_off_bh];

        float a00 = 0.f, a01 = 0.f, a10 = 0.f, a11 = 0.f;
        float a20 = 0.f, a21 = 0.f, a30 = 0.f, a31 = 0.f;

        if (t > 0) {
            // Wait for all 8 CTAs' h[t-1] pushes into hbuf[p]
            if (p == 0) { mbar_wait_cluster(mbar0, (uint32_t)ph0); ph0 ^= 1; }
            else        { mbar_wait_cluster(mbar1, (uint32_t)ph1); ph1 ^= 1; }

            const float* hb = hbuf + p * 2048;      // [512][4]
            const float* wp = w_T + kbase * 64 + hq * 4;
            const float* hp = hb + kbase * 4 + bp * 2;
            #pragma unroll 8
            for (int k = 0; k < 64; k++) {
                float4 wv = *(const float4*)(wp + k * 64);
                float2 hv = *(const float2*)(hp + k * 4);
                a00 += wv.x * hv.x;  a01 += wv.x * hv.y;
                a10 += wv.y * hv.x;  a11 += wv.y * hv.y;
                a20 += wv.z * hv.x;  a21 += wv.z * hv.y;
                a30 += wv.w * hv.x;  a31 += wv.w * hv.y;
            }
            // Partials: output o = b_local*64 + h_local
            float* pr = psum + ks * 256;
            int o0 = (2 * bp + 0) * 64 + 4 * hq;
            int o1 = (2 * bp + 1) * 64 + 4 * hq;
            *(float4*)&pr[o0] = make_float4(a00, a10, a20, a30);
            *(float4*)&pr[o1] = make_float4(a01, a11, a21, a31);
        }
        __syncthreads();

        // Reduce k-split partials, add xw, relu
        float v = xwv;
        if (t > 0) {
            #pragma unroll
            for (int s = 0; s < 8; s++) v += psum[s * 256 + tid];
        }
        v = fmaxf(v, 0.0f);

        stage[rh * 4 + rb] = v;
        out[(size_t)t * (BB * HH) + out_off_bh] = v;
        if (has_hfinal && t == TT - 1) {
            out[(size_t)TT * BB * HH + out_off_bh] = v;
        }
        __syncthreads();   // stage complete (and psum free for next step)

        if (t < TT - 1) {
            const int pn = p ^ 1;
            // Push this CTA's h slice (64h x 4b = 1KB) to all 8 cluster CTAs,
            // into hbuf[pn][64*r + q][0..3].
            const uint32_t dst_base =
                smem_base + (uint32_t)(SM_HBUF + pn * 2048 + ((int)r * 64) * 4) * 4u;
            #pragma unroll
            for (int i = 0; i < 2; i++) {
                int idx = tid + i * 256;   // 0..511
                int rk  = idx >> 6;        // target rank
                int q   = idx & 63;        // h_local within my slice
                float4 val = *(const float4*)&stage[q * 4];
                uint32_t dst = dst_base + (uint32_t)q * 16u;
                dsmem_st_b64(dst,     (uint32_t)rk, val.x, val.y);
                dsmem_st_b64(dst + 8, (uint32_t)rk, val.z, val.w);
            }
            __syncthreads();   // all pushes issued before the release-arrives
            if (tid < 8) {
                mbar_arrive_remote(pn == 0 ? mbar0 : mbar1, (uint32_t)tid);
            }
        }
    }

    // No CTA exits while peers' remote ops could still target its SMEM.
    asm volatile("barrier.cluster.arrive.aligned;" ::: "memory");
    asm volatile("barrier.cluster.wait.aligned;" ::: "memory");
}

// ---------------------------------------------------------------------------
extern "C" void kernel_launch(void* const* d_in, const int* in_sizes, int n_in,
                              void* d_out, int out_size) {
    const float* x   = (const float*)d_in[0];   // [T,B,I]
    const float* wih = (const float*)d_in[1];   // [H,I]
    const float* whh = (const float*)d_in[2];   // [H,H]
    const float* bih = (const float*)d_in[3];   // [H]
    const float* bhh = (const float*)d_in[4];   // [H]
    float* out = (float*)d_out;

    const int has_hfinal = (out_size >= TT * BB * HH + BB * HH) ? 1 : 0;

    cudaFuncSetAttribute(scan_kernel,
                         cudaFuncAttributeMaxDynamicSharedMemorySize,
                         SM_TOTAL_BYTES);

    dim3 g1(TT * BB / 64, HH / 64);   // (512, 8)
    phase1_kernel<<<g1, 256>>>(x, wih, bih, bhh);

    scan_kernel<<<128, 256, SM_TOTAL_BYTES>>>(whh, out, has_hfinal);
}